// round 13
// baseline (speedup 1.0000x reference)
#include <cuda_runtime.h>
#include <cuda_bf16.h>
#include <cstdint>
#include <cstddef>

#define NN 50000
#define NE 1600000
#define DD 128
#define RR 24
#define BB 8
#define KTOT (BB*DD + DD)     /* 1152 */
#define NR (NN*RR)            /* 1,200,000 */
#define WCF4 (KTOT*DD/4)      /* 36864 float4 in Wc */
#define WCBLK (WCF4/256)      /* 144 blocks convert Wc */

// ---------------- device scratch (no allocations allowed) ----------------
// g_cnt/g_cursor are zero at process start and re-zeroed at the END of every
// kernel_launch (tail of last gemm), so every call does identical work.
__device__ float g_h0[(size_t)NN * DD];
__device__ float g_h1[(size_t)NN * DD];
__device__ float g_A [(size_t)NN * KTOT];
__device__ float g_Wc[(size_t)KTOT * DD];
__device__ int   g_cnt[NR];
__device__ int   g_seg_start[NR];   // immutable segment starts
__device__ int   g_seg_off[NR];     // cursor; becomes segment END after place
__device__ int   g_sorted_src[NE];  // src ids grouped by (dst*R + type) segment
__device__ int   g_cursor;

// round-to-nearest tf32
__device__ __forceinline__ float tf32r(float x) {
    uint32_t u;
    asm("cvt.rna.tf32.f32 %0, %1;" : "=r"(u) : "f"(x));
    return __uint_as_float(u);
}

__device__ __forceinline__ void cp16(void* smem_ptr, const void* gptr, bool pred) {
    uint32_t s = (uint32_t)__cvta_generic_to_shared(smem_ptr);
    int sz = pred ? 16 : 0;
    asm volatile("cp.async.cg.shared.global [%0], [%1], 16, %2;\n"
                 :: "r"(s), "l"(gptr), "r"(sz));
}

// ---------------- setup kernels ----------------

__global__ void k_hist(const int* __restrict__ dst, const int* __restrict__ ety) {
    int e = blockIdx.x * blockDim.x + threadIdx.x;
    if (e < NE) atomicAdd(&g_cnt[dst[e] * RR + ety[e]], 1);
}

// Parallel segment-offset assignment: block-local scan + one global atomicAdd.
__global__ __launch_bounds__(256) void k_seg_assign() {
    __shared__ int wtot[8];
    __shared__ int s_base;
    int i = blockIdx.x * 256 + threadIdx.x;
    int lane = threadIdx.x & 31, wid = threadIdx.x >> 5;
    int c = (i < NR) ? g_cnt[i] : 0;
    int incl = c;
    #pragma unroll
    for (int d = 1; d < 32; d <<= 1) {
        int t = __shfl_up_sync(0xffffffffu, incl, d);
        if (lane >= d) incl += t;
    }
    if (lane == 31) wtot[wid] = incl;
    __syncthreads();
    if (threadIdx.x == 0) {
        int s = 0;
        #pragma unroll
        for (int j = 0; j < 8; j++) { int t = wtot[j]; wtot[j] = s; s += t; }
        s_base = atomicAdd(&g_cursor, s);
    }
    __syncthreads();
    if (i < NR) {
        int off = s_base + wtot[wid] + incl - c;
        g_seg_start[i] = off;
        g_seg_off[i]   = off;
    }
}

// place edges into segments; ALSO does the embedding gather (both exactly 1.6M threads).
__global__ void k_place_embed(const int* __restrict__ src, const int* __restrict__ dst,
                              const int* __restrict__ ety,
                              const int* __restrict__ x, const float4* __restrict__ emb) {
    int e = blockIdx.x * blockDim.x + threadIdx.x;
    if (e < NE) {
        int pos = atomicAdd(&g_seg_off[dst[e] * RR + ety[e]], 1);
        g_sorted_src[pos] = src[e];
    }
    if (e < NN * 32) {
        int n = e >> 5;
        int c = e & 31;
        ((float4*)g_h0)[e] = emb[(size_t)x[n] * 32 + c];
    }
}

// ---------------- aggregation: warp per node, run-length flush ----------------
// Flat edge list is relation-ordered within each node (staged in lane order),
// so edges form per-relation runs (avg len ~1.8). Accumulate a plain float4
// sum per run (4 FADD/edge) and apply the 8-weight outer product only at run
// boundaries (~18/node) -> ~30% fewer FMA-pipe ops than per-edge weighting.
// pk is pre-scaled: (r << 26) | (src * 32)  [float4 row index].
__global__ __launch_bounds__(256) void k_aggregate(int use_h1, const float* __restrict__ comp,
                                                   const float4* __restrict__ bases4,
                                                   const float4* __restrict__ root4) {
    const float4* __restrict__ h4 = (const float4*)(use_h1 ? g_h1 : g_h0);
    const int* __restrict__ srt = g_sorted_src;

    if (blockIdx.x < WCBLK) {
        int i = blockIdx.x * 256 + threadIdx.x;   // < WCF4 exactly
        float4 v = (i < BB * DD * DD / 4) ? bases4[i] : root4[i - BB * DD * DD / 4];
        v.x = tf32r(v.x); v.y = tf32r(v.y); v.z = tf32r(v.z); v.w = tf32r(v.w);
        ((float4*)g_Wc)[i] = v;
    }

    __shared__ float s_comp[RR * BB];
    __shared__ int   s_pk[8][128];        // rows 512B -> int4-aligned
    __shared__ float s_w[8][RR * BB];     // r*8 floats = 32B-aligned per relation
    for (int j = threadIdx.x; j < RR * BB; j += 256) s_comp[j] = comp[j];
    __syncthreads();

    const int lane = threadIdx.x & 31;
    const int wid  = threadIdx.x >> 5;
    const int n = (blockIdx.x * 256 + threadIdx.x) >> 5;   // 6250*8 = NN exactly

    int start_l = 0, cnt_l = 0;
    if (lane < RR) {
        start_l = g_seg_start[n * RR + lane];
        cnt_l   = g_seg_off[n * RR + lane] - start_l;
    }
    int incl = cnt_l;
    #pragma unroll
    for (int d = 1; d < 32; d <<= 1) {
        int t = __shfl_up_sync(0xffffffffu, incl, d);
        if (lane >= d) incl += t;
    }
    const int pos_l = incl - cnt_l;
    const int total = __shfl_sync(0xffffffffu, incl, 31);

    float z[BB][4];
    #pragma unroll
    for (int b = 0; b < BB; b++)
        #pragma unroll
        for (int j = 0; j < 4; j++) z[b][j] = 0.f;

    if (total <= 128) {
        for (int j = 0; j < cnt_l; j++)
            s_pk[wid][pos_l + j] = (__ldg(&srt[start_l + j]) * 32) | (lane << 26);
        if (lane < RR) {
            float invc = (cnt_l > 0) ? 1.0f / (float)cnt_l : 0.0f;
            #pragma unroll
            for (int b = 0; b < BB; b++)
                s_w[wid][lane * BB + b] = s_comp[lane * BB + b] * invc;
        }
        __syncwarp();

        // flush run-sum A against relation R's weights, then reset the sum
        #define FLUSH(R, A)                                                        \
        do {                                                                       \
            const float4* wq = (const float4*)&s_w[wid][(R) * BB];                 \
            float4 wa = wq[0], wb = wq[1];                                         \
            z[0][0] = fmaf(wa.x, (A).x, z[0][0]); z[0][1] = fmaf(wa.x, (A).y, z[0][1]); \
            z[0][2] = fmaf(wa.x, (A).z, z[0][2]); z[0][3] = fmaf(wa.x, (A).w, z[0][3]); \
            z[1][0] = fmaf(wa.y, (A).x, z[1][0]); z[1][1] = fmaf(wa.y, (A).y, z[1][1]); \
            z[1][2] = fmaf(wa.y, (A).z, z[1][2]); z[1][3] = fmaf(wa.y, (A).w, z[1][3]); \
            z[2][0] = fmaf(wa.z, (A).x, z[2][0]); z[2][1] = fmaf(wa.z, (A).y, z[2][1]); \
            z[2][2] = fmaf(wa.z, (A).z, z[2][2]); z[2][3] = fmaf(wa.z, (A).w, z[2][3]); \
            z[3][0] = fmaf(wa.w, (A).x, z[3][0]); z[3][1] = fmaf(wa.w, (A).y, z[3][1]); \
            z[3][2] = fmaf(wa.w, (A).z, z[3][2]); z[3][3] = fmaf(wa.w, (A).w, z[3][3]); \
            z[4][0] = fmaf(wb.x, (A).x, z[4][0]); z[4][1] = fmaf(wb.x, (A).y, z[4][1]); \
            z[4][2] = fmaf(wb.x, (A).z, z[4][2]); z[4][3] = fmaf(wb.x, (A).w, z[4][3]); \
            z[5][0] = fmaf(wb.y, (A).x, z[5][0]); z[5][1] = fmaf(wb.y, (A).y, z[5][1]); \
            z[5][2] = fmaf(wb.y, (A).z, z[5][2]); z[5][3] = fmaf(wb.y, (A).w, z[5][3]); \
            z[6][0] = fmaf(wb.z, (A).x, z[6][0]); z[6][1] = fmaf(wb.z, (A).y, z[6][1]); \
            z[6][2] = fmaf(wb.z, (A).z, z[6][2]); z[6][3] = fmaf(wb.z, (A).w, z[6][3]); \
            z[7][0] = fmaf(wb.w, (A).x, z[7][0]); z[7][1] = fmaf(wb.w, (A).y, z[7][1]); \
            z[7][2] = fmaf(wb.w, (A).z, z[7][2]); z[7][3] = fmaf(wb.w, (A).w, z[7][3]); \
        } while (0)

        // per-edge step with warp-uniform run-boundary flush
        #define EDGE_STEP(P, V)                                                    \
        do {                                                                       \
            int _r = ((unsigned)(P)) >> 26;                                        \
            if (_r != rprev) {                                                     \
                FLUSH(rprev, acc);                                                 \
                acc.x = 0.f; acc.y = 0.f; acc.z = 0.f; acc.w = 0.f;                \
                rprev = _r;                                                        \
            }                                                                      \
            acc.x += (V).x; acc.y += (V).y; acc.z += (V).z; acc.w += (V).w;        \
        } while (0)

        if (total > 0) {
            int rprev = ((unsigned)s_pk[wid][0]) >> 26;
            float4 acc = make_float4(0.f, 0.f, 0.f, 0.f);
            int k = 0;
            for (; k + 3 < total; k += 4) {
                int4 pk = *(const int4*)&s_pk[wid][k];   // k multiple of 4 -> aligned
                float4 v0 = __ldg(&h4[(pk.x & 0x03FFFFFF) + lane]);
                float4 v1 = __ldg(&h4[(pk.y & 0x03FFFFFF) + lane]);
                float4 v2 = __ldg(&h4[(pk.z & 0x03FFFFFF) + lane]);
                float4 v3 = __ldg(&h4[(pk.w & 0x03FFFFFF) + lane]);
                EDGE_STEP(pk.x, v0);
                EDGE_STEP(pk.y, v1);
                EDGE_STEP(pk.z, v2);
                EDGE_STEP(pk.w, v3);
            }
            for (; k < total; k++) {
                int p0 = s_pk[wid][k];
                float4 v0 = __ldg(&h4[(p0 & 0x03FFFFFF) + lane]);
                EDGE_STEP(p0, v0);
            }
            FLUSH(rprev, acc);
        }
        #undef EDGE_STEP
        #undef FLUSH
    } else {
        // fallback: per-segment loop (extremely high-degree node)
        for (int r = 0; r < RR; r++) {
            int c  = __shfl_sync(0xffffffffu, cnt_l, r);
            if (c == 0) continue;
            int e0 = __shfl_sync(0xffffffffu, start_l, r);
            int e1 = e0 + c;
            float4 a0 = make_float4(0.f, 0.f, 0.f, 0.f);
            float4 a1 = a0, a2 = a0, a3 = a0;
            int e = e0;
            for (; e + 3 < e1; e += 4) {
                float4 v0 = __ldg(&h4[__ldg(&srt[e])     * 32 + lane]);
                float4 v1 = __ldg(&h4[__ldg(&srt[e + 1]) * 32 + lane]);
                float4 v2 = __ldg(&h4[__ldg(&srt[e + 2]) * 32 + lane]);
                float4 v3 = __ldg(&h4[__ldg(&srt[e + 3]) * 32 + lane]);
                a0.x += v0.x; a0.y += v0.y; a0.z += v0.z; a0.w += v0.w;
                a1.x += v1.x; a1.y += v1.y; a1.z += v1.z; a1.w += v1.w;
                a2.x += v2.x; a2.y += v2.y; a2.z += v2.z; a2.w += v2.w;
                a3.x += v3.x; a3.y += v3.y; a3.z += v3.z; a3.w += v3.w;
            }
            for (; e < e1; e++) {
                float4 v0 = __ldg(&h4[__ldg(&srt[e]) * 32 + lane]);
                a0.x += v0.x; a0.y += v0.y; a0.z += v0.z; a0.w += v0.w;
            }
            float inv = 1.0f / (float)c;
            float m0 = ((a0.x + a1.x) + (a2.x + a3.x)) * inv;
            float m1 = ((a0.y + a1.y) + (a2.y + a3.y)) * inv;
            float m2 = ((a0.z + a1.z) + (a2.z + a3.z)) * inv;
            float m3 = ((a0.w + a1.w) + (a2.w + a3.w)) * inv;
            #pragma unroll
            for (int b = 0; b < BB; b++) {
                float w = s_comp[r * BB + b];
                z[b][0] = fmaf(w, m0, z[b][0]);
                z[b][1] = fmaf(w, m1, z[b][1]);
                z[b][2] = fmaf(w, m2, z[b][2]);
                z[b][3] = fmaf(w, m3, z[b][3]);
            }
        }
    }

    float4* Arow = (float4*)&g_A[(size_t)n * KTOT];
    #pragma unroll
    for (int b = 0; b < BB; b++) {
        float4 v;
        v.x = tf32r(z[b][0]); v.y = tf32r(z[b][1]);
        v.z = tf32r(z[b][2]); v.w = tf32r(z[b][3]);
        Arow[b * 32 + lane] = v;
    }
    float4 hv = __ldg(&h4[n * 32 + lane]);
    hv.x = tf32r(hv.x); hv.y = tf32r(hv.y); hv.z = tf32r(hv.z); hv.w = tf32r(hv.w);
    Arow[BB * 32 + lane] = hv;
}

// ---------------- tf32 tensor-core GEMM ----------------
#define GBM 128
#define GBK 16
#define NITER (KTOT / GBK)   /* 72 */

__global__ __launch_bounds__(256, 2) void k_gemm_tc(const float* __restrict__ bias,
                                                    float* __restrict__ outp, int relu,
                                                    int zero_next) {
    if (zero_next) {
        for (int i = blockIdx.x * 256 + threadIdx.x; i < NR / 4; i += gridDim.x * 256)
            ((int4*)g_cnt)[i] = make_int4(0, 0, 0, 0);
        if (blockIdx.x == 0 && threadIdx.x == 0) g_cursor = 0;
    }

    __shared__ float As[2][GBM][20];
    __shared__ float Bs[2][GBK][136];

    const int tid  = threadIdx.x;
    const int wid  = tid >> 5;
    const int lane = tid & 31;
    const int g    = lane >> 2;
    const int q    = lane & 3;
    const int warp_m = (wid >> 1) * 32;
    const int warp_n = (wid & 1) * 64;
    const int row0 = blockIdx.x * GBM;

    float acc[2][8][4];
    #pragma unroll
    for (int mi = 0; mi < 2; mi++)
        #pragma unroll
        for (int nj = 0; nj < 8; nj++)
            #pragma unroll
            for (int k = 0; k < 4; k++) acc[mi][nj][k] = 0.f;

    #define LOAD_TILES(K0, BUF)                                                   \
    do {                                                                          \
        _Pragma("unroll")                                                         \
        for (int j = 0; j < 2; j++) {                                             \
            int idx = tid + j * 256;                                              \
            int ar = idx >> 2, ac = (idx & 3) * 4;                                \
            bool ok = (row0 + ar) < NN;                                           \
            const float* src = ok ? &g_A[(size_t)(row0 + ar) * KTOT + (K0) + ac]  \
                                  : &g_A[0];                                      \
            cp16(&As[BUF][ar][ac], src, ok);                                      \
        }                                                                         \
        _Pragma("unroll")                                                         \
        for (int j = 0; j < 2; j++) {                                             \
            int idx = tid + j * 256;                                              \
            int br = idx >> 5, bc = (idx & 31) * 4;                               \
            cp16(&Bs[BUF][br][bc], &g_Wc[(size_t)((K0) + br) * DD + bc], true);   \
        }                                                                         \
    } while (0)

    LOAD_TILES(0, 0);
    asm volatile("cp.async.commit_group;");

    for (int it = 0; it < NITER; it++) {
        const int cur = it & 1;
        const int nxt = cur ^ 1;
        if (it + 1 < NITER) LOAD_TILES((it + 1) * GBK, nxt);
        asm volatile("cp.async.commit_group;");
        asm volatile("cp.async.wait_group 1;");
        __syncthreads();

        #pragma unroll
        for (int s = 0; s < 2; s++) {
            const int kb = s * 8;
            uint32_t af[2][4];
            uint32_t bf[8][2];
            #pragma unroll
            for (int mi = 0; mi < 2; mi++) {
                int m = warp_m + mi * 16 + g;
                af[mi][0] = __float_as_uint(As[cur][m][kb + q]);
                af[mi][1] = __float_as_uint(As[cur][m + 8][kb + q]);
                af[mi][2] = __float_as_uint(As[cur][m][kb + q + 4]);
                af[mi][3] = __float_as_uint(As[cur][m + 8][kb + q + 4]);
            }
            #pragma unroll
            for (int nj = 0; nj < 8; nj++) {
                int n = warp_n + nj * 8 + g;
                bf[nj][0] = __float_as_uint(Bs[cur][kb + q][n]);
                bf[nj][1] = __float_as_uint(Bs[cur][kb + q + 4][n]);
            }
            #pragma unroll
            for (int mi = 0; mi < 2; mi++)
                #pragma unroll
                for (int nj = 0; nj < 8; nj++) {
                    asm volatile(
                        "mma.sync.aligned.m16n8k8.row.col.f32.tf32.tf32.f32 "
                        "{%0,%1,%2,%3}, {%4,%5,%6,%7}, {%8,%9}, {%0,%1,%2,%3};\n"
                        : "+f"(acc[mi][nj][0]), "+f"(acc[mi][nj][1]),
                          "+f"(acc[mi][nj][2]), "+f"(acc[mi][nj][3])
                        : "r"(af[mi][0]), "r"(af[mi][1]), "r"(af[mi][2]), "r"(af[mi][3]),
                          "r"(bf[nj][0]), "r"(bf[nj][1]));
                }
        }
        __syncthreads();
    }

    float* dstb = outp ? outp : g_h1;
    #pragma unroll
    for (int mi = 0; mi < 2; mi++) {
        #pragma unroll
        for (int nj = 0; nj < 8; nj++) {
            int c  = warp_n + nj * 8 + q * 2;
            float b0 = __ldg(&bias[c]);
            float b1 = __ldg(&bias[c + 1]);
            int ra = row0 + warp_m + mi * 16 + g;
            int rb = ra + 8;
            float2 v0, v1;
            v0.x = acc[mi][nj][0] + b0; v0.y = acc[mi][nj][1] + b1;
            v1.x = acc[mi][nj][2] + b0; v1.y = acc[mi][nj][3] + b1;
            if (relu) {
                v0.x = fmaxf(v0.x, 0.f); v0.y = fmaxf(v0.y, 0.f);
                v1.x = fmaxf(v1.x, 0.f); v1.y = fmaxf(v1.y, 0.f);
            }
            if (ra < NN) *(float2*)&dstb[(size_t)ra * DD + c] = v0;
            if (rb < NN) *(float2*)&dstb[(size_t)rb * DD + c] = v1;
        }
    }
}

// ---------------- host launch ----------------
extern "C" void kernel_launch(void* const* d_in, const int* in_sizes, int n_in,
                              void* d_out, int out_size) {
    const int*   x      = (const int*)  d_in[0];
    const int*   ei     = (const int*)  d_in[1];
    const int*   ety    = (const int*)  d_in[2];
    const float* emb    = (const float*)d_in[3];
    const float* comp1  = (const float*)d_in[4];
    const float* bases1 = (const float*)d_in[5];
    const float* root1  = (const float*)d_in[6];
    const float* bias1  = (const float*)d_in[7];
    const float* comp2  = (const float*)d_in[8];
    const float* bases2 = (const float*)d_in[9];
    const float* root2  = (const float*)d_in[10];
    const float* bias2  = (const float*)d_in[11];
    const int* src = ei;
    const int* dst = ei + NE;
    float* out = (float*)d_out;

    const int gemm_blocks = (NN + GBM - 1) / GBM;   // 391
    const int agg_blocks  = NN / 8;                 // 6250, exact

    k_hist       <<<(NE + 255) / 256, 256>>>(dst, ety);                 // #1
    k_seg_assign <<<(NR + 255) / 256, 256>>>();                         // #2
    k_place_embed<<<NE / 256, 256>>>(src, dst, ety, x, (const float4*)emb); // #3
    k_aggregate  <<<agg_blocks, 256>>>(0, comp1,                        // #4 (profiled)
                                       (const float4*)bases1, (const float4*)root1);
    k_gemm_tc    <<<gemm_blocks, 256>>>(bias1, nullptr, 1, 0);          // #5
    k_aggregate  <<<agg_blocks, 256>>>(1, comp2,                        // #6
                                       (const float4*)bases2, (const float4*)root2);
    k_gemm_tc    <<<gemm_blocks, 256>>>(bias2, out, 0, 1);              // #7
}

// round 14
// speedup vs baseline: 1.0145x; 1.0145x over previous
#include <cuda_runtime.h>
#include <cuda_bf16.h>
#include <cstdint>
#include <cstddef>

#define NN 50000
#define NE 1600000
#define DD 128
#define RR 24
#define BB 8
#define KTOT (BB*DD + DD)     /* 1152 */
#define NR (NN*RR)            /* 1,200,000 */
#define WCF4 (KTOT*DD/4)      /* 36864 float4 in Wc */
#define WCBLK (WCF4/256)      /* 144 blocks convert Wc */

// ---------------- device scratch (no allocations allowed) ----------------
// g_cnt/g_cursor are zero at process start and re-zeroed at the END of every
// kernel_launch (tail of last gemm), so every call does identical work.
__device__ float g_h0[(size_t)NN * DD];
__device__ float g_h1[(size_t)NN * DD];
__device__ float g_A [(size_t)NN * KTOT];
__device__ float g_Wc[(size_t)KTOT * DD];
__device__ int   g_cnt[NR];
__device__ int   g_seg_start[NR];   // immutable segment starts
__device__ int   g_seg_off[NR];     // cursor; becomes segment END after place
__device__ int   g_sorted_src[NE];  // src ids grouped by (dst*R + type) segment
__device__ int   g_cursor;

// round-to-nearest tf32
__device__ __forceinline__ float tf32r(float x) {
    uint32_t u;
    asm("cvt.rna.tf32.f32 %0, %1;" : "=r"(u) : "f"(x));
    return __uint_as_float(u);
}

__device__ __forceinline__ void cp16(void* smem_ptr, const void* gptr, bool pred) {
    uint32_t s = (uint32_t)__cvta_generic_to_shared(smem_ptr);
    int sz = pred ? 16 : 0;
    asm volatile("cp.async.cg.shared.global [%0], [%1], 16, %2;\n"
                 :: "r"(s), "l"(gptr), "r"(sz));
}

// ---------------- setup kernels ----------------

__global__ void k_hist(const int* __restrict__ dst, const int* __restrict__ ety) {
    int e = blockIdx.x * blockDim.x + threadIdx.x;
    if (e < NE) atomicAdd(&g_cnt[dst[e] * RR + ety[e]], 1);
}

// Parallel segment-offset assignment: block-local scan + one global atomicAdd.
__global__ __launch_bounds__(256) void k_seg_assign() {
    __shared__ int wtot[8];
    __shared__ int s_base;
    int i = blockIdx.x * 256 + threadIdx.x;
    int lane = threadIdx.x & 31, wid = threadIdx.x >> 5;
    int c = (i < NR) ? g_cnt[i] : 0;
    int incl = c;
    #pragma unroll
    for (int d = 1; d < 32; d <<= 1) {
        int t = __shfl_up_sync(0xffffffffu, incl, d);
        if (lane >= d) incl += t;
    }
    if (lane == 31) wtot[wid] = incl;
    __syncthreads();
    if (threadIdx.x == 0) {
        int s = 0;
        #pragma unroll
        for (int j = 0; j < 8; j++) { int t = wtot[j]; wtot[j] = s; s += t; }
        s_base = atomicAdd(&g_cursor, s);
    }
    __syncthreads();
    if (i < NR) {
        int off = s_base + wtot[wid] + incl - c;
        g_seg_start[i] = off;
        g_seg_off[i]   = off;
    }
}

// place edges into segments; ALSO does the embedding gather (both exactly 1.6M threads).
__global__ void k_place_embed(const int* __restrict__ src, const int* __restrict__ dst,
                              const int* __restrict__ ety,
                              const int* __restrict__ x, const float4* __restrict__ emb) {
    int e = blockIdx.x * blockDim.x + threadIdx.x;
    if (e < NE) {
        int pos = atomicAdd(&g_seg_off[dst[e] * RR + ety[e]], 1);
        g_sorted_src[pos] = src[e];
    }
    if (e < NN * 32) {
        int n = e >> 5;
        int c = e & 31;
        ((float4*)g_h0)[e] = emb[(size_t)x[n] * 32 + c];
    }
}

// ---------------- aggregation: warp per node, flat edge loop ----------------
// Round-12 formulation (best known: 141 us/layer, latency plateau).
__global__ __launch_bounds__(256) void k_aggregate(int use_h1, const float* __restrict__ comp,
                                                   const float4* __restrict__ bases4,
                                                   const float4* __restrict__ root4) {
    const float4* __restrict__ h4 = (const float4*)(use_h1 ? g_h1 : g_h0);
    const int* __restrict__ srt = g_sorted_src;

    if (blockIdx.x < WCBLK) {
        int i = blockIdx.x * 256 + threadIdx.x;   // < WCF4 exactly
        float4 v = (i < BB * DD * DD / 4) ? bases4[i] : root4[i - BB * DD * DD / 4];
        v.x = tf32r(v.x); v.y = tf32r(v.y); v.z = tf32r(v.z); v.w = tf32r(v.w);
        ((float4*)g_Wc)[i] = v;
    }

    __shared__ float s_comp[RR * BB];
    __shared__ int   s_pk[8][128];        // rows 512B -> int4-aligned
    __shared__ float s_w[8][RR * BB];     // r*8 floats = 32B-aligned per relation
    for (int j = threadIdx.x; j < RR * BB; j += 256) s_comp[j] = comp[j];
    __syncthreads();

    const int lane = threadIdx.x & 31;
    const int wid  = threadIdx.x >> 5;
    const int n = (blockIdx.x * 256 + threadIdx.x) >> 5;   // 6250*8 = NN exactly

    int start_l = 0, cnt_l = 0;
    if (lane < RR) {
        start_l = g_seg_start[n * RR + lane];
        cnt_l   = g_seg_off[n * RR + lane] - start_l;
    }
    int incl = cnt_l;
    #pragma unroll
    for (int d = 1; d < 32; d <<= 1) {
        int t = __shfl_up_sync(0xffffffffu, incl, d);
        if (lane >= d) incl += t;
    }
    const int pos_l = incl - cnt_l;
    const int total = __shfl_sync(0xffffffffu, incl, 31);

    float z[BB][4];
    #pragma unroll
    for (int b = 0; b < BB; b++)
        #pragma unroll
        for (int j = 0; j < 4; j++) z[b][j] = 0.f;

    if (total <= 128) {
        for (int j = 0; j < cnt_l; j++)
            s_pk[wid][pos_l + j] = __ldg(&srt[start_l + j]) | (lane << 16);
        if (lane < RR) {
            float invc = (cnt_l > 0) ? 1.0f / (float)cnt_l : 0.0f;
            #pragma unroll
            for (int b = 0; b < BB; b++)
                s_w[wid][lane * BB + b] = s_comp[lane * BB + b] * invc;
        }
        __syncwarp();

        // per-edge FMA block: z[b][j] += w[b] * v[j], weights via 2x LDS.128
        #define EDGE_FMA(P, V)                                                     \
        do {                                                                       \
            const float4* wq = (const float4*)&s_w[wid][((P) >> 16) * BB];         \
            float4 wa = wq[0], wb = wq[1];                                         \
            z[0][0] = fmaf(wa.x, (V).x, z[0][0]); z[0][1] = fmaf(wa.x, (V).y, z[0][1]); \
            z[0][2] = fmaf(wa.x, (V).z, z[0][2]); z[0][3] = fmaf(wa.x, (V).w, z[0][3]); \
            z[1][0] = fmaf(wa.y, (V).x, z[1][0]); z[1][1] = fmaf(wa.y, (V).y, z[1][1]); \
            z[1][2] = fmaf(wa.y, (V).z, z[1][2]); z[1][3] = fmaf(wa.y, (V).w, z[1][3]); \
            z[2][0] = fmaf(wa.z, (V).x, z[2][0]); z[2][1] = fmaf(wa.z, (V).y, z[2][1]); \
            z[2][2] = fmaf(wa.z, (V).z, z[2][2]); z[2][3] = fmaf(wa.z, (V).w, z[2][3]); \
            z[3][0] = fmaf(wa.w, (V).x, z[3][0]); z[3][1] = fmaf(wa.w, (V).y, z[3][1]); \
            z[3][2] = fmaf(wa.w, (V).z, z[3][2]); z[3][3] = fmaf(wa.w, (V).w, z[3][3]); \
            z[4][0] = fmaf(wb.x, (V).x, z[4][0]); z[4][1] = fmaf(wb.x, (V).y, z[4][1]); \
            z[4][2] = fmaf(wb.x, (V).z, z[4][2]); z[4][3] = fmaf(wb.x, (V).w, z[4][3]); \
            z[5][0] = fmaf(wb.y, (V).x, z[5][0]); z[5][1] = fmaf(wb.y, (V).y, z[5][1]); \
            z[5][2] = fmaf(wb.y, (V).z, z[5][2]); z[5][3] = fmaf(wb.y, (V).w, z[5][3]); \
            z[6][0] = fmaf(wb.z, (V).x, z[6][0]); z[6][1] = fmaf(wb.z, (V).y, z[6][1]); \
            z[6][2] = fmaf(wb.z, (V).z, z[6][2]); z[6][3] = fmaf(wb.z, (V).w, z[6][3]); \
            z[7][0] = fmaf(wb.w, (V).x, z[7][0]); z[7][1] = fmaf(wb.w, (V).y, z[7][1]); \
            z[7][2] = fmaf(wb.w, (V).z, z[7][2]); z[7][3] = fmaf(wb.w, (V).w, z[7][3]); \
        } while (0)

        int k = 0;
        for (; k + 3 < total; k += 4) {
            int4 pk = *(const int4*)&s_pk[wid][k];   // k multiple of 4 -> aligned
            float4 v0 = __ldg(&h4[(pk.x & 0xFFFF) * 32 + lane]);
            float4 v1 = __ldg(&h4[(pk.y & 0xFFFF) * 32 + lane]);
            float4 v2 = __ldg(&h4[(pk.z & 0xFFFF) * 32 + lane]);
            float4 v3 = __ldg(&h4[(pk.w & 0xFFFF) * 32 + lane]);
            EDGE_FMA(pk.x, v0);
            EDGE_FMA(pk.y, v1);
            EDGE_FMA(pk.z, v2);
            EDGE_FMA(pk.w, v3);
        }
        for (; k < total; k++) {
            int p0 = s_pk[wid][k];
            float4 v0 = __ldg(&h4[(p0 & 0xFFFF) * 32 + lane]);
            EDGE_FMA(p0, v0);
        }
        #undef EDGE_FMA
    } else {
        // fallback: per-segment loop (extremely high-degree node)
        for (int r = 0; r < RR; r++) {
            int c  = __shfl_sync(0xffffffffu, cnt_l, r);
            if (c == 0) continue;
            int e0 = __shfl_sync(0xffffffffu, start_l, r);
            int e1 = e0 + c;
            float4 a0 = make_float4(0.f, 0.f, 0.f, 0.f);
            float4 a1 = a0, a2 = a0, a3 = a0;
            int e = e0;
            for (; e + 3 < e1; e += 4) {
                float4 v0 = __ldg(&h4[__ldg(&srt[e])     * 32 + lane]);
                float4 v1 = __ldg(&h4[__ldg(&srt[e + 1]) * 32 + lane]);
                float4 v2 = __ldg(&h4[__ldg(&srt[e + 2]) * 32 + lane]);
                float4 v3 = __ldg(&h4[__ldg(&srt[e + 3]) * 32 + lane]);
                a0.x += v0.x; a0.y += v0.y; a0.z += v0.z; a0.w += v0.w;
                a1.x += v1.x; a1.y += v1.y; a1.z += v1.z; a1.w += v1.w;
                a2.x += v2.x; a2.y += v2.y; a2.z += v2.z; a2.w += v2.w;
                a3.x += v3.x; a3.y += v3.y; a3.z += v3.z; a3.w += v3.w;
            }
            for (; e < e1; e++) {
                float4 v0 = __ldg(&h4[__ldg(&srt[e]) * 32 + lane]);
                a0.x += v0.x; a0.y += v0.y; a0.z += v0.z; a0.w += v0.w;
            }
            float inv = 1.0f / (float)c;
            float m0 = ((a0.x + a1.x) + (a2.x + a3.x)) * inv;
            float m1 = ((a0.y + a1.y) + (a2.y + a3.y)) * inv;
            float m2 = ((a0.z + a1.z) + (a2.z + a3.z)) * inv;
            float m3 = ((a0.w + a1.w) + (a2.w + a3.w)) * inv;
            #pragma unroll
            for (int b = 0; b < BB; b++) {
                float w = s_comp[r * BB + b];
                z[b][0] = fmaf(w, m0, z[b][0]);
                z[b][1] = fmaf(w, m1, z[b][1]);
                z[b][2] = fmaf(w, m2, z[b][2]);
                z[b][3] = fmaf(w, m3, z[b][3]);
            }
        }
    }

    float4* Arow = (float4*)&g_A[(size_t)n * KTOT];
    #pragma unroll
    for (int b = 0; b < BB; b++) {
        float4 v;
        v.x = tf32r(z[b][0]); v.y = tf32r(z[b][1]);
        v.z = tf32r(z[b][2]); v.w = tf32r(z[b][3]);
        Arow[b * 32 + lane] = v;
    }
    float4 hv = __ldg(&h4[n * 32 + lane]);
    hv.x = tf32r(hv.x); hv.y = tf32r(hv.y); hv.z = tf32r(hv.z); hv.w = tf32r(hv.w);
    Arow[BB * 32 + lane] = hv;
}

// ---------------- tf32 tensor-core GEMM: 4-stage cp.async pipeline ----------
// out[N,128] = g_A[N,1152] @ g_Wc[1152,128] + bias (optional relu)
// BM=128, BN=128, BK=16, 256 threads, dynamic smem (4 stages, 75.8 KB).
#define GBM 128
#define GBK 16
#define GSTG 4
#define NITER (KTOT / GBK)   /* 72 */
#define A_ST_F (GBM * 20)    /* floats per A stage (stride 20, conflict-free) */
#define B_ST_F (GBK * 136)   /* floats per B stage (stride 136, conflict-free) */
#define GEMM_SMEM_BYTES (GSTG * (A_ST_F + B_ST_F) * 4)   /* 75776 */

__global__ __launch_bounds__(256, 2) void k_gemm_tc(const float* __restrict__ bias,
                                                    float* __restrict__ outp, int relu,
                                                    int zero_next) {
    if (zero_next) {
        for (int i = blockIdx.x * 256 + threadIdx.x; i < NR / 4; i += gridDim.x * 256)
            ((int4*)g_cnt)[i] = make_int4(0, 0, 0, 0);
        if (blockIdx.x == 0 && threadIdx.x == 0) g_cursor = 0;
    }

    extern __shared__ float smem[];
    float* Asb = smem;                   // [GSTG][GBM][20]
    float* Bsb = smem + GSTG * A_ST_F;   // [GSTG][GBK][136]

    const int tid  = threadIdx.x;
    const int wid  = tid >> 5;
    const int lane = tid & 31;
    const int g    = lane >> 2;
    const int q    = lane & 3;
    const int warp_m = (wid >> 1) * 32;
    const int warp_n = (wid & 1) * 64;
    const int row0 = blockIdx.x * GBM;

    float acc[2][8][4];
    #pragma unroll
    for (int mi = 0; mi < 2; mi++)
        #pragma unroll
        for (int nj = 0; nj < 8; nj++)
            #pragma unroll
            for (int k = 0; k < 4; k++) acc[mi][nj][k] = 0.f;

    // A tile: 128x16 floats = 512 float4; 2 per thread
    // B tile: 16x128 floats = 512 float4; 2 per thread
    #define LOAD_TILES(K0, ST)                                                    \
    do {                                                                          \
        _Pragma("unroll")                                                         \
        for (int j = 0; j < 2; j++) {                                             \
            int idx = tid + j * 256;                                              \
            int ar = idx >> 2, ac = (idx & 3) * 4;                                \
            bool ok = (row0 + ar) < NN;                                           \
            const float* src = ok ? &g_A[(size_t)(row0 + ar) * KTOT + (K0) + ac]  \
                                  : &g_A[0];                                      \
            cp16(&Asb[(ST) * A_ST_F + ar * 20 + ac], src, ok);                    \
        }                                                                         \
        _Pragma("unroll")                                                         \
        for (int j = 0; j < 2; j++) {                                             \
            int idx = tid + j * 256;                                              \
            int br = idx >> 5, bc = (idx & 31) * 4;                               \
            cp16(&Bsb[(ST) * B_ST_F + br * 136 + bc],                             \
                 &g_Wc[(size_t)((K0) + br) * DD + bc], true);                     \
        }                                                                         \
    } while (0)

    // prologue: prefetch stages 0..2 (groups 0..2)
    #pragma unroll
    for (int p = 0; p < GSTG - 1; p++) {
        LOAD_TILES(p * GBK, p);
        asm volatile("cp.async.commit_group;");
    }

    for (int it = 0; it < NITER; it++) {
        if (it + GSTG - 1 < NITER) LOAD_TILES((it + GSTG - 1) * GBK, (it + GSTG - 1) & (GSTG - 1));
        asm volatile("cp.async.commit_group;");
        asm volatile("cp.async.wait_group 3;");   // group 'it' complete
        __syncthreads();

        const int cur = it & (GSTG - 1);
        const float* Acur = &Asb[cur * A_ST_F];
        const float* Bcur = &Bsb[cur * B_ST_F];

        #pragma unroll
        for (int s = 0; s < 2; s++) {
            const int kb = s * 8;
            uint32_t af[2][4];
            uint32_t bf[8][2];
            #pragma unroll
            for (int mi = 0; mi < 2; mi++) {
                int m = warp_m + mi * 16 + g;
                af[mi][0] = __float_as_uint(Acur[m * 20 + kb + q]);
                af[mi][1] = __float_as_uint(Acur[(m + 8) * 20 + kb + q]);
                af[mi][2] = __float_as_uint(Acur[m * 20 + kb + q + 4]);
                af[mi][3] = __float_as_uint(Acur[(m + 8) * 20 + kb + q + 4]);
            }
            #pragma unroll
            for (int nj = 0; nj < 8; nj++) {
                int n = warp_n + nj * 8 + g;
                bf[nj][0] = __float_as_uint(Bcur[(kb + q) * 136 + n]);
                bf[nj][1] = __float_as_uint(Bcur[(kb + q + 4) * 136 + n]);
            }
            #pragma unroll
            for (int mi = 0; mi < 2; mi++)
                #pragma unroll
                for (int nj = 0; nj < 8; nj++) {
                    asm volatile(
                        "mma.sync.aligned.m16n8k8.row.col.f32.tf32.tf32.f32 "
                        "{%0,%1,%2,%3}, {%4,%5,%6,%7}, {%8,%9}, {%0,%1,%2,%3};\n"
                        : "+f"(acc[mi][nj][0]), "+f"(acc[mi][nj][1]),
                          "+f"(acc[mi][nj][2]), "+f"(acc[mi][nj][3])
                        : "r"(af[mi][0]), "r"(af[mi][1]), "r"(af[mi][2]), "r"(af[mi][3]),
                          "r"(bf[nj][0]), "r"(bf[nj][1]));
                }
        }
        __syncthreads();
    }

    float* dstb = outp ? outp : g_h1;
    #pragma unroll
    for (int mi = 0; mi < 2; mi++) {
        #pragma unroll
        for (int nj = 0; nj < 8; nj++) {
            int c  = warp_n + nj * 8 + q * 2;
            float b0 = __ldg(&bias[c]);
            float b1 = __ldg(&bias[c + 1]);
            int ra = row0 + warp_m + mi * 16 + g;
            int rb = ra + 8;
            float2 v0, v1;
            v0.x = acc[mi][nj][0] + b0; v0.y = acc[mi][nj][1] + b1;
            v1.x = acc[mi][nj][2] + b0; v1.y = acc[mi][nj][3] + b1;
            if (relu) {
                v0.x = fmaxf(v0.x, 0.f); v0.y = fmaxf(v0.y, 0.f);
                v1.x = fmaxf(v1.x, 0.f); v1.y = fmaxf(v1.y, 0.f);
            }
            if (ra < NN) *(float2*)&dstb[(size_t)ra * DD + c] = v0;
            if (rb < NN) *(float2*)&dstb[(size_t)rb * DD + c] = v1;
        }
    }
}

// ---------------- host launch ----------------
extern "C" void kernel_launch(void* const* d_in, const int* in_sizes, int n_in,
                              void* d_out, int out_size) {
    const int*   x      = (const int*)  d_in[0];
    const int*   ei     = (const int*)  d_in[1];
    const int*   ety    = (const int*)  d_in[2];
    const float* emb    = (const float*)d_in[3];
    const float* comp1  = (const float*)d_in[4];
    const float* bases1 = (const float*)d_in[5];
    const float* root1  = (const float*)d_in[6];
    const float* bias1  = (const float*)d_in[7];
    const float* comp2  = (const float*)d_in[8];
    const float* bases2 = (const float*)d_in[9];
    const float* root2  = (const float*)d_in[10];
    const float* bias2  = (const float*)d_in[11];
    const int* src = ei;
    const int* dst = ei + NE;
    float* out = (float*)d_out;

    // opt in to >48KB dynamic smem for the GEMM (idempotent, capture-legal)
    cudaFuncSetAttribute(k_gemm_tc, cudaFuncAttributeMaxDynamicSharedMemorySize,
                         GEMM_SMEM_BYTES);

    const int gemm_blocks = (NN + GBM - 1) / GBM;   // 391
    const int agg_blocks  = NN / 8;                 // 6250, exact

    k_hist       <<<(NE + 255) / 256, 256>>>(dst, ety);                 // #1
    k_seg_assign <<<(NR + 255) / 256, 256>>>();                         // #2
    k_place_embed<<<NE / 256, 256>>>(src, dst, ety, x, (const float4*)emb); // #3
    k_aggregate  <<<agg_blocks, 256>>>(0, comp1,                        // #4 (profiled)
                                       (const float4*)bases1, (const float4*)root1);
    k_gemm_tc    <<<gemm_blocks, 256, GEMM_SMEM_BYTES>>>(bias1, nullptr, 1, 0);  // #5
    k_aggregate  <<<agg_blocks, 256>>>(1, comp2,                        // #6
                                       (const float4*)bases2, (const float4*)root2);
    k_gemm_tc    <<<gemm_blocks, 256, GEMM_SMEM_BYTES>>>(bias2, out, 0, 1);      // #7
}